// round 2
// baseline (speedup 1.0000x reference)
#include <cuda_runtime.h>
#include <cuda_bf16.h>
#include <math.h>

// Problem constants: B=8, N=4096, C=1024, H=16, dh=64
#define BB 8
#define NN 4096
#define CC 1024
#define HH 16
#define DH 64
#define M_ROWS (BB * NN)          // 32768
#define QKV_COLS (3 * CC)         // 3072

// ---------------- static scratch (no runtime allocation allowed) -------------
__device__ __align__(128) float g_Y[(size_t)M_ROWS * QKV_COLS];   // qkv: [32768, 3072]
__device__ __align__(128) float g_Z[(size_t)M_ROWS * CC];         // attn@v reshaped: [32768, 1024]
__device__ __align__(128) float g_Spart[(size_t)BB * HH * 8 * DH * DH]; // partial grams [bh][seg][64][64]
__device__ __align__(128) float g_attn[(size_t)BB * HH * DH * DH];      // softmaxed attn
__device__ __align__(128) float g_sumsq[BB * 2 * CC];                   // per-(b,col) sumsq for q,k

// ---------------------------------------------------------------------------
// K1/K5: fp32 SGEMM, C[M,N] = A[M,K] @ B[K,N] (+bias). 128x128x16 tile,
// 256 threads, 8x8 register tile, float4 global loads. M%128==0, N%128==0,
// K%16==0 guaranteed by problem shapes.
// ---------------------------------------------------------------------------
__global__ __launch_bounds__(256) void sgemm_kernel(
    const float* __restrict__ A, const float* __restrict__ B,
    float* __restrict__ C, const float* __restrict__ bias,
    int M, int N, int K) {
  constexpr int BM = 128, BN = 128, BK = 16;
  __shared__ float As[BK][BM];   // transposed A tile
  __shared__ float Bs[BK][BN];
  const int tid = threadIdx.x;
  const int bm = blockIdx.y * BM;
  const int bn = blockIdx.x * BN;
  const int tx = tid & 15;       // 16 thread cols
  const int ty = tid >> 4;       // 16 thread rows

  float acc[8][8] = {};

  const float* Ab = A + (size_t)bm * K;
  const float* Bb = B + bn;

  for (int k0 = 0; k0 < K; k0 += BK) {
#pragma unroll
    for (int i = 0; i < 2; ++i) {
      int lin = tid + i * 256;                 // 0..511 float4 slots
      int ar  = lin >> 2;                      // 0..127
      int ac4 = (lin & 3) << 2;                // 0,4,8,12
      float4 av = *(const float4*)(Ab + (size_t)ar * K + k0 + ac4);
      As[ac4 + 0][ar] = av.x;
      As[ac4 + 1][ar] = av.y;
      As[ac4 + 2][ar] = av.z;
      As[ac4 + 3][ar] = av.w;
      int br  = lin >> 5;                      // 0..15
      int bc4 = (lin & 31) << 2;               // 0..124
      *(float4*)&Bs[br][bc4] = *(const float4*)(Bb + (size_t)(k0 + br) * N + bc4);
    }
    __syncthreads();
#pragma unroll
    for (int kk = 0; kk < BK; ++kk) {
      float af[8], bf[8];
      *(float4*)&af[0] = *(float4*)&As[kk][ty * 8];
      *(float4*)&af[4] = *(float4*)&As[kk][ty * 8 + 4];
      *(float4*)&bf[0] = *(float4*)&Bs[kk][tx * 8];
      *(float4*)&bf[4] = *(float4*)&Bs[kk][tx * 8 + 4];
#pragma unroll
      for (int i = 0; i < 8; ++i)
#pragma unroll
        for (int j = 0; j < 8; ++j)
          acc[i][j] += af[i] * bf[j];
    }
    __syncthreads();
  }

  float bv[8];
  if (bias) {
#pragma unroll
    for (int j = 0; j < 8; ++j) bv[j] = bias[bn + tx * 8 + j];
  } else {
#pragma unroll
    for (int j = 0; j < 8; ++j) bv[j] = 0.0f;
  }
#pragma unroll
  for (int i = 0; i < 8; ++i) {
    int row = bm + ty * 8 + i;
    float* Crow = C + (size_t)row * N + bn + tx * 8;
    float4 o0 = make_float4(acc[i][0] + bv[0], acc[i][1] + bv[1],
                            acc[i][2] + bv[2], acc[i][3] + bv[3]);
    float4 o1 = make_float4(acc[i][4] + bv[4], acc[i][5] + bv[5],
                            acc[i][6] + bv[6], acc[i][7] + bv[7]);
    *(float4*)(Crow + 0) = o0;
    *(float4*)(Crow + 4) = o1;
  }
}

// ---------------------------------------------------------------------------
// K2: per-batch column sum-of-squares over the token axis for q,k columns
// (cols 0..2047 of Y). grid = (2048/64, B), 256 threads.
// ---------------------------------------------------------------------------
__global__ __launch_bounds__(256) void sumsq_kernel() {
  const int b = blockIdx.y;
  const int col = blockIdx.x * 64 + (threadIdx.x & 63);
  const int part = threadIdx.x >> 6;   // 0..3
  const float* base = g_Y + (size_t)b * NN * QKV_COLS + col;
  float s = 0.0f;
  for (int n = part; n < NN; n += 4) {
    float v = base[(size_t)n * QKV_COLS];
    s += v * v;
  }
  __shared__ float red[256];
  red[threadIdx.x] = s;
  __syncthreads();
  if (part == 0) {
    int t = threadIdx.x;
    g_sumsq[b * 2048 + col] = red[t] + red[t + 64] + red[t + 128] + red[t + 192];
  }
}

// ---------------------------------------------------------------------------
// K3: partial gram S[d][e] = sum_n q[d,n] * k[e,n] per (b,h), split into 8
// token segments of 512 for parallelism. grid = (8, B*H), 256 threads,
// each thread accumulates a 4x4 patch of the 64x64 gram.
// ---------------------------------------------------------------------------
__global__ __launch_bounds__(256) void gram_kernel() {
  const int seg = blockIdx.x;          // 0..7
  const int bh = blockIdx.y;           // 0..127
  const int b = bh >> 4, h = bh & 15;
  __shared__ float qs[32][64];
  __shared__ float ks[32][64];
  const int tid = threadIdx.x;
  const int tx = tid & 15, ty = tid >> 4;
  float acc[4][4] = {};

  const float* Yq = g_Y + (size_t)(b * NN + seg * 512) * QKV_COLS + h * DH;
  const float* Yk = Yq + CC;           // k block is +1024 cols

  for (int ch = 0; ch < 16; ++ch) {    // 16 chunks of 32 tokens
#pragma unroll
    for (int i = 0; i < 2; ++i) {
      int lin = tid + i * 256;         // 0..511 float4 slots (32 tok x 16 f4)
      int r = lin >> 4;
      int c4 = (lin & 15) << 2;
      size_t off = (size_t)(ch * 32 + r) * QKV_COLS + c4;
      *(float4*)&qs[r][c4] = *(const float4*)(Yq + off);
      *(float4*)&ks[r][c4] = *(const float4*)(Yk + off);
    }
    __syncthreads();
#pragma unroll
    for (int r = 0; r < 32; ++r) {
      float4 qa = *(float4*)&qs[r][ty * 4];
      float4 ka = *(float4*)&ks[r][tx * 4];
      float qv[4] = {qa.x, qa.y, qa.z, qa.w};
      float kv[4] = {ka.x, ka.y, ka.z, ka.w};
#pragma unroll
      for (int i = 0; i < 4; ++i)
#pragma unroll
        for (int j = 0; j < 4; ++j)
          acc[i][j] += qv[i] * kv[j];
    }
    __syncthreads();
  }

  float* Sout = g_Spart + (size_t)(bh * 8 + seg) * (DH * DH);
#pragma unroll
  for (int i = 0; i < 4; ++i)
#pragma unroll
    for (int j = 0; j < 4; ++j)
      Sout[(ty * 4 + i) * DH + tx * 4 + j] = acc[i][j];
}

// ---------------------------------------------------------------------------
// K3b: reduce partial grams, apply 1/(||q|| ||k||) * temperature, softmax
// over e (row-wise, 64 wide). grid = B*H, 256 threads.
// ---------------------------------------------------------------------------
__global__ __launch_bounds__(256) void softmax_kernel(const float* __restrict__ temp) {
  const int bh = blockIdx.x;
  const int b = bh >> 4, h = bh & 15;
  __shared__ float S[64][65];
  __shared__ float nqv[64], nkv[64];
  const int tid = threadIdx.x;

  if (tid < 64) {
    nqv[tid] = fmaxf(sqrtf(g_sumsq[b * 2048 + h * DH + tid]), 1e-12f);
    nkv[tid] = fmaxf(sqrtf(g_sumsq[b * 2048 + CC + h * DH + tid]), 1e-12f);
  }
  __syncthreads();

  const float tp = temp[h];
  for (int idx = tid; idx < DH * DH; idx += 256) {
    float s = 0.0f;
#pragma unroll
    for (int seg = 0; seg < 8; ++seg)
      s += g_Spart[(size_t)(bh * 8 + seg) * (DH * DH) + idx];
    int d = idx >> 6, e = idx & 63;
    S[d][e] = s / (nqv[d] * nkv[e]) * tp;
  }
  __syncthreads();

  if (tid < 64) {
    int d = tid;
    float m = -3.402823466e38f;
    for (int e = 0; e < 64; ++e) m = fmaxf(m, S[d][e]);
    float sum = 0.0f;
    for (int e = 0; e < 64; ++e) {
      float ex = expf(S[d][e] - m);
      S[d][e] = ex;
      sum += ex;
    }
    float inv = 1.0f / sum;
    float* Ao = g_attn + (size_t)bh * (DH * DH) + d * DH;
    for (int e = 0; e < 64; ++e) Ao[e] = S[d][e] * inv;
  }
}

// ---------------------------------------------------------------------------
// K4: Z[bn, h*64+d] = sum_e attn[b,h,d,e] * v[b,h,e,n].
// v[b,h,e,n] = Y[bn, 2048 + h*64 + e] (contiguous in e per token!).
// grid = (N/256, B*H); each thread owns one token, computes 64 outputs.
// attn tile lives in smem (broadcast reads).
// ---------------------------------------------------------------------------
__global__ __launch_bounds__(256) void attnv_kernel() {
  const int bh = blockIdx.y;
  const int b = bh >> 4, h = bh & 15;
  const int n = blockIdx.x * 256 + threadIdx.x;
  __shared__ float As[64][64];
  const int tid = threadIdx.x;

  const float* Ag = g_attn + (size_t)bh * (DH * DH);
#pragma unroll
  for (int i = 0; i < 4; ++i) {
    int lin = tid + i * 256;                   // 0..1023 float4 slots
    *(float4*)&As[lin >> 4][(lin & 15) << 2] = *(const float4*)(Ag + lin * 4);
  }
  __syncthreads();

  const float* v = g_Y + (size_t)(b * NN + n) * QKV_COLS + 2 * CC + h * DH;
  float z[64];
#pragma unroll
  for (int d = 0; d < 64; ++d) z[d] = 0.0f;

#pragma unroll
  for (int c = 0; c < 4; ++c) {                // chunks of 16 e-values
    float4 v0 = *(const float4*)(v + c * 16 + 0);
    float4 v1 = *(const float4*)(v + c * 16 + 4);
    float4 v2 = *(const float4*)(v + c * 16 + 8);
    float4 v3 = *(const float4*)(v + c * 16 + 12);
#pragma unroll
    for (int d = 0; d < 64; ++d) {
      const float4* Ad = (const float4*)&As[d][c * 16];
      float4 a0 = Ad[0], a1 = Ad[1], a2 = Ad[2], a3 = Ad[3];
      float s = a0.x * v0.x + a0.y * v0.y + a0.z * v0.z + a0.w * v0.w;
      s += a1.x * v1.x + a1.y * v1.y + a1.z * v1.z + a1.w * v1.w;
      s += a2.x * v2.x + a2.y * v2.y + a2.z * v2.z + a2.w * v2.w;
      s += a3.x * v3.x + a3.y * v3.y + a3.z * v3.z + a3.w * v3.w;
      z[d] += s;
    }
  }

  float* zo = g_Z + (size_t)(b * NN + n) * CC + h * DH;
#pragma unroll
  for (int d4 = 0; d4 < 16; ++d4)
    *(float4*)(zo + d4 * 4) =
        make_float4(z[d4 * 4], z[d4 * 4 + 1], z[d4 * 4 + 2], z[d4 * 4 + 3]);
}

// ---------------------------------------------------------------------------
extern "C" void kernel_launch(void* const* d_in, const int* in_sizes, int n_in,
                              void* d_out, int out_size) {
  const float* x      = (const float*)d_in[0];  // [8,4096,1024]
  const float* w_qkv  = (const float*)d_in[1];  // [1024,3072]
  const float* temp   = (const float*)d_in[2];  // [16,1,1]
  const float* w_proj = (const float*)d_in[3];  // [1024,1024]
  const float* b_proj = (const float*)d_in[4];  // [1024]
  float* out = (float*)d_out;                   // [8,4096,1024]

  // Cache symbol addresses: after the first call (the harness's correctness
  // run), the captured region contains kernel launches only.
  static float* Y = nullptr;
  static float* Z = nullptr;
  if (Y == nullptr) {
    cudaGetSymbolAddress((void**)&Y, g_Y);
    cudaGetSymbolAddress((void**)&Z, g_Z);
  }

  // K1: qkv = x @ w_qkv  -> g_Y [32768, 3072]
  sgemm_kernel<<<dim3(QKV_COLS / 128, M_ROWS / 128), 256>>>(
      x, w_qkv, Y, nullptr, M_ROWS, QKV_COLS, CC);

  // K2: column sum-of-squares for q,k (normalization folded into softmax)
  sumsq_kernel<<<dim3(32, BB), 256>>>();

  // K3: raw grams q.k^T per (b,h), 8 token segments
  gram_kernel<<<dim3(8, BB * HH), 256>>>();

  // K3b: reduce segments, scale by 1/(|q||k|)*temp, softmax
  softmax_kernel<<<BB * HH, 256>>>(temp);

  // K4: Z = attn @ v, written in [B,N,C] layout
  attnv_kernel<<<dim3(NN / 256, BB * HH), 256>>>();

  // K5: out = Z @ w_proj + b_proj
  sgemm_kernel<<<dim3(CC / 128, M_ROWS / 128), 256>>>(
      Z, w_proj, out, b_proj, M_ROWS, CC, CC);
}